// round 10
// baseline (speedup 1.0000x reference)
#include <cuda_runtime.h>
#include <cuda_fp16.h>

// GIN model, restructured:
//   conv(x) = segment_sum(relu(x[src]@W1x + ea@W1e + b1), dst) @ W2 + (deg+1)*b2
// Node tables fp16; tensor-core GEMMs (mma.m16n8k16 f16->f32); middle two
// GEMMs fused (h stays in smem); CSR gather with packed int4 edge metadata.

#define HD 128
#define MAX_N 100000
#define MAX_E 1600000

__device__ __half g_P[(long long)MAX_N * HD];     // pre-MLP table (both layers)
__device__ __half g_agg16[(long long)MAX_N * HD]; // aggregation (fp16)
__device__ __half g_x16[(long long)MAX_N * 64];   // x converted to fp16
__device__ __half g_wt11[128 * 64];               // W11x^T fp16 [n][k]
__device__ __half g_wt12[128 * 128];              // W12^T
__device__ __half g_wt21[128 * 128];              // W21x^T
__device__ __half g_wt22[128 * 128];              // W22^T
__device__ int    g_cnt[MAX_N];
__device__ int    g_fill[MAX_N];
__device__ int    g_rowptr[MAX_N + 1];
__device__ int    g_bsum[128];
__device__ int    g_boff[128];
__device__ int4   g_meta[MAX_E];                  // (src, bits(ea0), bits(ea1), 0)

__device__ __forceinline__ void cp16(void* smem_dst, const void* gsrc, int src_bytes) {
    unsigned s = (unsigned)__cvta_generic_to_shared(smem_dst);
    asm volatile("cp.async.ca.shared.global [%0], [%1], 16, %2;"
                 :: "r"(s), "l"(gsrc), "r"(src_bytes));
}
__device__ __forceinline__ void cp_commit() { asm volatile("cp.async.commit_group;"); }
template <int NN>
__device__ __forceinline__ void cp_wait() {
    asm volatile("cp.async.wait_group %0;" :: "n"(NN));
}
__device__ __forceinline__ void mma16816(float* d, const unsigned* a, const unsigned* b) {
    asm volatile("mma.sync.aligned.m16n8k16.row.col.f32.f16.f16.f32 "
                 "{%0,%1,%2,%3}, {%4,%5,%6,%7}, {%8,%9}, {%0,%1,%2,%3};"
                 : "+f"(d[0]), "+f"(d[1]), "+f"(d[2]), "+f"(d[3])
                 : "r"(a[0]), "r"(a[1]), "r"(a[2]), "r"(a[3]),
                   "r"(b[0]), "r"(b[1]));
}

// ============================== CSR build ==================================
__global__ void count_kernel(const int* __restrict__ ei, int* __restrict__ cnt, int E) {
    int e = blockIdx.x * blockDim.x + threadIdx.x;
    if (e < E) atomicAdd(&cnt[ei[E + e]], 1);
}
__global__ void scan_reduce_kernel(const int* __restrict__ cnt, int* __restrict__ bsum, int N) {
    __shared__ int sh[256];
    int base = blockIdx.x * 1024;
    int s = 0;
    for (int i = threadIdx.x; i < 1024; i += 256) {
        int idx = base + i;
        if (idx < N) s += cnt[idx];
    }
    sh[threadIdx.x] = s; __syncthreads();
    for (int off = 128; off > 0; off >>= 1) {
        if (threadIdx.x < off) sh[threadIdx.x] += sh[threadIdx.x + off];
        __syncthreads();
    }
    if (threadIdx.x == 0) bsum[blockIdx.x] = sh[0];
}
__global__ void scan_bsums_kernel(const int* __restrict__ bsum, int* __restrict__ boff,
                                  int nb, int* __restrict__ rowptr, int N, int E) {
    __shared__ int sh[128];
    int t = threadIdx.x;
    int v = (t < nb) ? bsum[t] : 0;
    sh[t] = v; __syncthreads();
#pragma unroll
    for (int off = 1; off < 128; off <<= 1) {
        int u = (t >= off) ? sh[t - off] : 0;
        __syncthreads();
        sh[t] += u;
        __syncthreads();
    }
    if (t < nb) boff[t] = sh[t] - v;
    if (t == 0) rowptr[N] = E;
}
__global__ void scan_block_kernel(const int* __restrict__ cnt, const int* __restrict__ boff,
                                  int* __restrict__ rowptr, int N) {
    __shared__ int sh[1024];
    const int tid = threadIdx.x;
    const int idx = blockIdx.x * 1024 + tid;
    int v = (idx < N) ? cnt[idx] : 0;
    sh[tid] = v; __syncthreads();
#pragma unroll
    for (int off = 1; off < 1024; off <<= 1) {
        int t = (tid >= off) ? sh[tid - off] : 0;
        __syncthreads();
        sh[tid] += t;
        __syncthreads();
    }
    if (idx < N) rowptr[idx] = boff[blockIdx.x] + sh[tid] - v;
}
__global__ void fill_kernel(const int* __restrict__ ei, const float* __restrict__ ea,
                            const int* __restrict__ rowptr, int* __restrict__ fill,
                            int4* __restrict__ meta, int E) {
    int e = blockIdx.x * blockDim.x + threadIdx.x;
    if (e >= E) return;
    int dst = ei[E + e];
    int slot = rowptr[dst] + atomicAdd(&fill[dst], 1);
    float2 ev = *(const float2*)(ea + 2 * e);
    meta[slot] = make_int4(ei[e], __float_as_int(ev.x), __float_as_int(ev.y), 0);
}

// ========================= conversion prepasses ============================
__global__ void cvt_x_kernel(const float* __restrict__ x, __half* __restrict__ xh, int n4) {
    int i = blockIdx.x * blockDim.x + threadIdx.x;
    if (i < n4) {
        float4 v = ((const float4*)x)[i];
        __half2 a = __floats2half2_rn(v.x, v.y);
        __half2 b = __floats2half2_rn(v.z, v.w);
        uint2 o;
        o.x = *(unsigned*)&a;
        o.y = *(unsigned*)&b;
        ((uint2*)xh)[i] = o;
    }
}
__global__ void cvt_weights_kernel(const float* __restrict__ W11, const float* __restrict__ W12,
                                   const float* __restrict__ W21, const float* __restrict__ W22,
                                   __half* __restrict__ wt11, __half* __restrict__ wt12,
                                   __half* __restrict__ wt21, __half* __restrict__ wt22) {
    int idx = blockIdx.x * blockDim.x + threadIdx.x;
    if (idx < 8192) {
        int n = idx >> 6, k = idx & 63;
        wt11[idx] = __float2half(W11[k * 128 + n]);
    } else if (idx < 8192 + 16384) {
        int i = idx - 8192;
        int n = i >> 7, k = i & 127;
        wt12[i] = __float2half(W12[k * 128 + n]);
    } else if (idx < 8192 + 32768) {
        int i = idx - 8192 - 16384;
        int n = i >> 7, k = i & 127;
        wt21[i] = __float2half(W21[k * 128 + n]);
    } else if (idx < 8192 + 49152) {
        int i = idx - 8192 - 32768;
        int n = i >> 7, k = i & 127;
        wt22[i] = __float2half(W22[k * 128 + n]);
    }
}

// ======================= tensor-core GEMM (single) =========================
template <int K, typename OutT, bool BIAS, bool RELU>
__global__ __launch_bounds__(256, 2)
void hgemm_kernel(const __half* __restrict__ A, const __half* __restrict__ Wt,
                  OutT* __restrict__ C, const float* __restrict__ bias,
                  const int* __restrict__ rowptr, int N)
{
    constexpr int BS_LD = K + 8;
    constexpr int AS_LD = 40;
    extern __shared__ __half sh[];
    __half* Bs = sh;
    __half* As = sh + 128 * BS_LD;

    const int tid  = threadIdx.x;
    const int lane = tid & 31;
    const int wid  = tid >> 5;
    const int wm   = (wid & 3) * 32;
    const int wn   = (wid >> 2) * 64;
    const int row0 = blockIdx.x * 128;

    {
        int r = tid >> 1;
        int cb = (tid & 1) * (K / 2);
#pragma unroll
        for (int j = 0; j < K / 16; ++j)
            cp16(&Bs[r * BS_LD + cb + j * 8], &Wt[r * K + cb + j * 8], 16);
    }
    auto loadA = [&](int buf, int k0) {
        int r = tid >> 1;
        int h0 = (tid & 1) * 16;
        int row = row0 + r;
        int ok = (row < N) ? 16 : 0;
        const __half* ap = &A[(long long)row * K + k0 + h0];
        __half* dp = &As[(buf * 128 + r) * AS_LD + h0];
        cp16(dp,     ap,     ok);
        cp16(dp + 8, ap + 8, ok);
    };
    loadA(0, 0);
    cp_commit();

    float d[2][8][4];
#pragma unroll
    for (int i = 0; i < 2; ++i)
#pragma unroll
        for (int j = 0; j < 8; ++j)
#pragma unroll
            for (int p = 0; p < 4; ++p) d[i][j][p] = 0.f;

    const int r_ = lane >> 2;
    const int c_ = (lane & 3) * 2;
    constexpr int nt = K / 32;

#pragma unroll 1
    for (int t = 0; t < nt; ++t) {
        const int buf = t & 1;
        if (t + 1 < nt) { loadA(buf ^ 1, (t + 1) * 32); cp_commit(); cp_wait<1>(); }
        else            { cp_wait<0>(); }
        __syncthreads();
#pragma unroll
        for (int ks = 0; ks < 2; ++ks) {
            const int kk = ks * 16;
            unsigned a[2][4], b[8][2];
#pragma unroll
            for (int i = 0; i < 2; ++i) {
                const __half* base = &As[(buf * 128 + wm + i * 16 + r_) * AS_LD + kk + c_];
                a[i][0] = *(const unsigned*)base;
                a[i][1] = *(const unsigned*)(base + 8 * AS_LD);
                a[i][2] = *(const unsigned*)(base + 8);
                a[i][3] = *(const unsigned*)(base + 8 * AS_LD + 8);
            }
#pragma unroll
            for (int j = 0; j < 8; ++j) {
                const __half* bb = &Bs[(wn + j * 8 + r_) * BS_LD + t * 32 + kk + c_];
                b[j][0] = *(const unsigned*)bb;
                b[j][1] = *(const unsigned*)(bb + 8);
            }
#pragma unroll
            for (int i = 0; i < 2; ++i)
#pragma unroll
                for (int j = 0; j < 8; ++j)
                    mma16816(d[i][j], a[i], b[j]);
        }
        __syncthreads();
    }

#pragma unroll
    for (int i = 0; i < 2; ++i) {
#pragma unroll
        for (int hf = 0; hf < 2; ++hf) {
            int row = row0 + wm + i * 16 + hf * 8 + r_;
            if (row >= N) continue;
            float mult = 0.f;
            if (BIAS) mult = (float)(rowptr[row + 1] - rowptr[row]) + 1.0f;
#pragma unroll
            for (int j = 0; j < 8; ++j) {
                float v0 = d[i][j][hf * 2 + 0];
                float v1 = d[i][j][hf * 2 + 1];
                int col = wn + j * 8 + c_;
                if (BIAS) { v0 += mult * bias[col]; v1 += mult * bias[col + 1]; }
                if (RELU) { v0 = fmaxf(v0, 0.f); v1 = fmaxf(v1, 0.f); }
                if constexpr (sizeof(OutT) == 2) {
                    __half2 hv = __floats2half2_rn(v0, v1);
                    *(__half2*)((__half*)C + (long long)row * 128 + col) = hv;
                } else {
                    *(float2*)((float*)C + (long long)row * 128 + col) = make_float2(v0, v1);
                }
            }
        }
    }
}

// =================== fused dual GEMM: agg -> h -> P2 =======================
// h = relu(agg@W12 + (deg+1)*b12) kept in smem; P2 = h @ W21x -> global fp16.
__global__ __launch_bounds__(256, 2)
void hgemm_dual_kernel(const __half* __restrict__ A, const __half* __restrict__ Wt1,
                       const __half* __restrict__ Wt2, __half* __restrict__ C,
                       const float* __restrict__ bias, const int* __restrict__ rowptr,
                       int N)
{
    constexpr int BS_LD = 136;   // 128 + 8
    constexpr int AS_LD = 40;
    extern __shared__ __half sh[];
    __half* Bs1 = sh;                        // W12 tile, later h tile [128][136]
    __half* Bs2 = sh + 128 * BS_LD;          // W21 tile [128][136]
    __half* As  = sh + 2 * 128 * BS_LD;      // [2][128][40]

    const int tid  = threadIdx.x;
    const int lane = tid & 31;
    const int wid  = tid >> 5;
    const int wm   = (wid & 3) * 32;
    const int wn   = (wid >> 2) * 64;
    const int row0 = blockIdx.x * 128;

    {
        int r = tid >> 1;
        int cb = (tid & 1) * 64;
#pragma unroll
        for (int j = 0; j < 8; ++j) {
            cp16(&Bs1[r * BS_LD + cb + j * 8], &Wt1[r * 128 + cb + j * 8], 16);
            cp16(&Bs2[r * BS_LD + cb + j * 8], &Wt2[r * 128 + cb + j * 8], 16);
        }
    }
    auto loadA = [&](int buf, int k0) {
        int r = tid >> 1;
        int h0 = (tid & 1) * 16;
        int row = row0 + r;
        int ok = (row < N) ? 16 : 0;
        const __half* ap = &A[(long long)row * 128 + k0 + h0];
        __half* dp = &As[(buf * 128 + r) * AS_LD + h0];
        cp16(dp,     ap,     ok);
        cp16(dp + 8, ap + 8, ok);
    };
    cp_commit();          // group: Bs1+Bs2
    loadA(0, 0);
    cp_commit();          // group: As tile 0

    float d[2][8][4];
#pragma unroll
    for (int i = 0; i < 2; ++i)
#pragma unroll
        for (int j = 0; j < 8; ++j)
#pragma unroll
            for (int p = 0; p < 4; ++p) d[i][j][p] = 0.f;

    const int r_ = lane >> 2;
    const int c_ = (lane & 3) * 2;

    // ---------------- GEMM1: agg @ W12 ----------------
#pragma unroll 1
    for (int t = 0; t < 4; ++t) {
        const int buf = t & 1;
        if (t + 1 < 4) { loadA(buf ^ 1, (t + 1) * 32); cp_commit(); cp_wait<1>(); }
        else           { cp_wait<0>(); }
        __syncthreads();
#pragma unroll
        for (int ks = 0; ks < 2; ++ks) {
            const int kk = ks * 16;
            unsigned a[2][4], b[8][2];
#pragma unroll
            for (int i = 0; i < 2; ++i) {
                const __half* base = &As[(buf * 128 + wm + i * 16 + r_) * AS_LD + kk + c_];
                a[i][0] = *(const unsigned*)base;
                a[i][1] = *(const unsigned*)(base + 8 * AS_LD);
                a[i][2] = *(const unsigned*)(base + 8);
                a[i][3] = *(const unsigned*)(base + 8 * AS_LD + 8);
            }
#pragma unroll
            for (int j = 0; j < 8; ++j) {
                const __half* bb = &Bs1[(wn + j * 8 + r_) * BS_LD + t * 32 + kk + c_];
                b[j][0] = *(const unsigned*)bb;
                b[j][1] = *(const unsigned*)(bb + 8);
            }
#pragma unroll
            for (int i = 0; i < 2; ++i)
#pragma unroll
                for (int j = 0; j < 8; ++j)
                    mma16816(d[i][j], a[i], b[j]);
        }
        __syncthreads();
    }

    // epilogue 1: h -> Bs1 (overwrite W12 tile; all reads done, synced above)
#pragma unroll
    for (int i = 0; i < 2; ++i) {
#pragma unroll
        for (int hf = 0; hf < 2; ++hf) {
            int ln = wm + i * 16 + hf * 8 + r_;
            int row = row0 + ln;
            float mult = (row < N) ? (float)(rowptr[row + 1] - rowptr[row]) + 1.0f : 0.f;
#pragma unroll
            for (int j = 0; j < 8; ++j) {
                float v0 = d[i][j][hf * 2 + 0] + mult * bias[wn + j * 8 + c_];
                float v1 = d[i][j][hf * 2 + 1] + mult * bias[wn + j * 8 + c_ + 1];
                v0 = fmaxf(v0, 0.f); v1 = fmaxf(v1, 0.f);
                __half2 hv = __floats2half2_rn(v0, v1);
                *(__half2*)&Bs1[ln * BS_LD + wn + j * 8 + c_] = hv;
            }
        }
    }
    __syncthreads();

    // ---------------- GEMM2: h @ W21 ----------------
#pragma unroll
    for (int i = 0; i < 2; ++i)
#pragma unroll
        for (int j = 0; j < 8; ++j)
#pragma unroll
            for (int p = 0; p < 4; ++p) d[i][j][p] = 0.f;

#pragma unroll 1
    for (int t = 0; t < 4; ++t) {
#pragma unroll
        for (int ks = 0; ks < 2; ++ks) {
            const int kk = t * 32 + ks * 16;
            unsigned a[2][4], b[8][2];
#pragma unroll
            for (int i = 0; i < 2; ++i) {
                const __half* base = &Bs1[(wm + i * 16 + r_) * BS_LD + kk + c_];
                a[i][0] = *(const unsigned*)base;
                a[i][1] = *(const unsigned*)(base + 8 * BS_LD);
                a[i][2] = *(const unsigned*)(base + 8);
                a[i][3] = *(const unsigned*)(base + 8 * BS_LD + 8);
            }
#pragma unroll
            for (int j = 0; j < 8; ++j) {
                const __half* bb = &Bs2[(wn + j * 8 + r_) * BS_LD + kk + c_];
                b[j][0] = *(const unsigned*)bb;
                b[j][1] = *(const unsigned*)(bb + 8);
            }
#pragma unroll
            for (int i = 0; i < 2; ++i)
#pragma unroll
                for (int j = 0; j < 8; ++j)
                    mma16816(d[i][j], a[i], b[j]);
        }
    }

#pragma unroll
    for (int i = 0; i < 2; ++i) {
#pragma unroll
        for (int hf = 0; hf < 2; ++hf) {
            int row = row0 + wm + i * 16 + hf * 8 + r_;
            if (row >= N) continue;
#pragma unroll
            for (int j = 0; j < 8; ++j) {
                int col = wn + j * 8 + c_;
                __half2 hv = __floats2half2_rn(d[i][j][hf * 2 + 0], d[i][j][hf * 2 + 1]);
                *(__half2*)&C[(long long)row * 128 + col] = hv;
            }
        }
    }
}

// ========================= CSR gather-aggregate ============================
__device__ __forceinline__ float4 cvtP4(uint2 raw) {
    __half2 h0 = *(__half2*)&raw.x;
    __half2 h1 = *(__half2*)&raw.y;
    float2 f0 = __half22float2(h0);
    float2 f1 = __half22float2(h1);
    return make_float4(f0.x, f0.y, f1.x, f1.y);
}

__global__ __launch_bounds__(256)
void gather_kernel(const int* __restrict__ rowptr, const int4* __restrict__ meta,
                   const __half* __restrict__ P, __half* __restrict__ agg,
                   const float* __restrict__ w0, const float* __restrict__ w1,
                   const float* __restrict__ b, int N)
{
    const int lane = threadIdx.x & 31;
    const int c = lane * 4;
    const int warp = blockIdx.x * (blockDim.x >> 5) + (threadIdx.x >> 5);
    const int nwarps = gridDim.x * (blockDim.x >> 5);

    const float4 wa = *(const float4*)(w0 + c);
    const float4 wb = *(const float4*)(w1 + c);
    const float4 bb = *(const float4*)(b + c);

    for (int n = warp; n < N; n += nwarps) {
        const int s = rowptr[n];
        const int e = rowptr[n + 1];

        // self loop (ea = 1,1)
        float4 ps = cvtP4(*(const uint2*)(P + (long long)n * HD + c));
        float4 acc;
        acc.x = fmaxf(ps.x + wa.x + wb.x + bb.x, 0.f);
        acc.y = fmaxf(ps.y + wa.y + wb.y + bb.y, 0.f);
        acc.z = fmaxf(ps.z + wa.z + wb.z + bb.z, 0.f);
        acc.w = fmaxf(ps.w + wa.w + wb.w + bb.w, 0.f);

        int j = s;
        for (; j + 8 <= e; j += 8) {
            uint2 raw[8];
            int4 mt[8];
#pragma unroll
            for (int q = 0; q < 8; ++q) {
                mt[q] = meta[j + q];
                raw[q] = *(const uint2*)(P + (long long)mt[q].x * HD + c);
            }
#pragma unroll
            for (int q = 0; q < 8; ++q) {
                float ex = __int_as_float(mt[q].y);
                float ey = __int_as_float(mt[q].z);
                float4 p = cvtP4(raw[q]);
                acc.x += fmaxf(fmaf(ex, wa.x, fmaf(ey, wb.x, p.x + bb.x)), 0.f);
                acc.y += fmaxf(fmaf(ex, wa.y, fmaf(ey, wb.y, p.y + bb.y)), 0.f);
                acc.z += fmaxf(fmaf(ex, wa.z, fmaf(ey, wb.z, p.z + bb.z)), 0.f);
                acc.w += fmaxf(fmaf(ex, wa.w, fmaf(ey, wb.w, p.w + bb.w)), 0.f);
            }
        }
        if (j + 4 <= e) {
            uint2 raw[4];
            int4 mt[4];
#pragma unroll
            for (int q = 0; q < 4; ++q) {
                mt[q] = meta[j + q];
                raw[q] = *(const uint2*)(P + (long long)mt[q].x * HD + c);
            }
#pragma unroll
            for (int q = 0; q < 4; ++q) {
                float ex = __int_as_float(mt[q].y);
                float ey = __int_as_float(mt[q].z);
                float4 p = cvtP4(raw[q]);
                acc.x += fmaxf(fmaf(ex, wa.x, fmaf(ey, wb.x, p.x + bb.x)), 0.f);
                acc.y += fmaxf(fmaf(ex, wa.y, fmaf(ey, wb.y, p.y + bb.y)), 0.f);
                acc.z += fmaxf(fmaf(ex, wa.z, fmaf(ey, wb.z, p.z + bb.z)), 0.f);
                acc.w += fmaxf(fmaf(ex, wa.w, fmaf(ey, wb.w, p.w + bb.w)), 0.f);
            }
            j += 4;
        }
        for (; j < e; ++j) {
            int4 mq = meta[j];
            float ex = __int_as_float(mq.y);
            float ey = __int_as_float(mq.z);
            float4 p = cvtP4(*(const uint2*)(P + (long long)mq.x * HD + c));
            acc.x += fmaxf(fmaf(ex, wa.x, fmaf(ey, wb.x, p.x + bb.x)), 0.f);
            acc.y += fmaxf(fmaf(ex, wa.y, fmaf(ey, wb.y, p.y + bb.y)), 0.f);
            acc.z += fmaxf(fmaf(ex, wa.z, fmaf(ey, wb.z, p.z + bb.z)), 0.f);
            acc.w += fmaxf(fmaf(ex, wa.w, fmaf(ey, wb.w, p.w + bb.w)), 0.f);
        }
        __half2 o0 = __floats2half2_rn(acc.x, acc.y);
        __half2 o1 = __floats2half2_rn(acc.z, acc.w);
        uint2 st;
        st.x = *(unsigned*)&o0;
        st.y = *(unsigned*)&o1;
        *(uint2*)(agg + (long long)n * HD + c) = st;
    }
}

// ---------------------------------------------------------------------------
extern "C" void kernel_launch(void* const* d_in, const int* in_sizes, int n_in,
                              void* d_out, int out_size)
{
    const float* x   = (const float*)d_in[0];
    const int*   ei  = (const int*)d_in[1];
    const float* ea  = (const float*)d_in[2];
    const float* W11 = (const float*)d_in[3];
    const float* b11 = (const float*)d_in[4];
    const float* W12 = (const float*)d_in[5];
    const float* b12 = (const float*)d_in[6];
    const float* W21 = (const float*)d_in[7];
    const float* b21 = (const float*)d_in[8];
    const float* W22 = (const float*)d_in[9];
    const float* b22 = (const float*)d_in[10];
    float* out = (float*)d_out;

    const int IN_DIM = 64;
    const int N = in_sizes[0] / IN_DIM;
    const int E = in_sizes[1] / 2;

    __half *P, *agg16, *x16, *wt11, *wt12, *wt21, *wt22;
    int *cnt, *fill, *rowptr, *bsum, *boff;
    int4* meta;
    cudaGetSymbolAddress((void**)&P,      g_P);
    cudaGetSymbolAddress((void**)&agg16,  g_agg16);
    cudaGetSymbolAddress((void**)&x16,    g_x16);
    cudaGetSymbolAddress((void**)&wt11,   g_wt11);
    cudaGetSymbolAddress((void**)&wt12,   g_wt12);
    cudaGetSymbolAddress((void**)&wt21,   g_wt21);
    cudaGetSymbolAddress((void**)&wt22,   g_wt22);
    cudaGetSymbolAddress((void**)&cnt,    g_cnt);
    cudaGetSymbolAddress((void**)&fill,   g_fill);
    cudaGetSymbolAddress((void**)&rowptr, g_rowptr);
    cudaGetSymbolAddress((void**)&bsum,   g_bsum);
    cudaGetSymbolAddress((void**)&boff,   g_boff);
    cudaGetSymbolAddress((void**)&meta,   g_meta);

    const int gemm_blocks = (N + 127) / 128;
    const int gath_blocks = 148 * 16;
    const int nb = (N + 1023) / 1024;
    const int smem128 = (128 * (128 + 8) + 2 * 128 * 40) * 2;        // 55296 B
    const int smem64  = (128 * (64 + 8)  + 2 * 128 * 40) * 2;        // 38912 B
    const int smemDual = (2 * 128 * 136 + 2 * 128 * 40) * 2;         // 90112 B

    static int attr_set = 0;
    if (!attr_set) {
        cudaFuncSetAttribute(hgemm_kernel<64,  __half, false, false>,
                             cudaFuncAttributeMaxDynamicSharedMemorySize, smem64);
        cudaFuncSetAttribute(hgemm_dual_kernel,
                             cudaFuncAttributeMaxDynamicSharedMemorySize, smemDual);
        cudaFuncSetAttribute(hgemm_kernel<128, float,  true,  false>,
                             cudaFuncAttributeMaxDynamicSharedMemorySize, smem128);
        attr_set = 1;
    }

    // ---- CSR build ----
    cudaMemsetAsync(cnt,  0, N * sizeof(int));
    cudaMemsetAsync(fill, 0, N * sizeof(int));
    count_kernel<<<(E + 255) / 256, 256>>>(ei, cnt, E);
    scan_reduce_kernel<<<nb, 256>>>(cnt, bsum, N);
    scan_bsums_kernel<<<1, 128>>>(bsum, boff, nb, rowptr, N, E);
    scan_block_kernel<<<nb, 1024>>>(cnt, boff, rowptr, N);
    fill_kernel<<<(E + 255) / 256, 256>>>(ei, ea, rowptr, fill, meta, E);

    // ---- conversions ----
    cvt_x_kernel<<<(N * 16 + 255) / 256, 256>>>(x, x16, N * 16);
    cvt_weights_kernel<<<(8192 + 49152 + 255) / 256, 256>>>(
        W11, W12, W21, W22, wt11, wt12, wt21, wt22);

    // ---- layer 1 ----
    hgemm_kernel<64, __half, false, false><<<gemm_blocks, 256, smem64>>>(
        x16, wt11, P, nullptr, nullptr, N);
    gather_kernel<<<gath_blocks, 256>>>(rowptr, meta, P, agg16,
                                        W11 + 64 * 128, W11 + 65 * 128, b11, N);
    // h = relu(agg@W12 + (deg+1)b12) in smem; P2 = h@W21x
    hgemm_dual_kernel<<<gemm_blocks, 256, smemDual>>>(
        agg16, wt12, wt21, P, b12, rowptr, N);

    // ---- layer 2 ----
    gather_kernel<<<gath_blocks, 256>>>(rowptr, meta, P, agg16,
                                        W21 + 128 * 128, W21 + 129 * 128, b21, N);
    hgemm_kernel<128, float, true, false><<<gemm_blocks, 256, smem128>>>(
        agg16, wt22, out, b22, rowptr, N);
}

// round 11
// speedup vs baseline: 1.1709x; 1.1709x over previous
#include <cuda_runtime.h>
#include <cuda_fp16.h>

// GIN model, restructured (R9 base + 8-byte packed edge meta + CSR-build
// side-stream overlap under graph capture):
//   conv(x) = segment_sum(relu(x[src]@W1x + ea@W1e + b1), dst) @ W2 + (deg+1)*b2
// Node tables fp16; GEMMs on tensor cores (mma.m16n8k16 f16->f32).

#define HD 128
#define MAX_N 100000
#define MAX_E 1600000

__device__ __half g_P[(long long)MAX_N * HD];     // pre-MLP table
__device__ __half g_agg16[(long long)MAX_N * HD]; // aggregation (fp16)
__device__ __half g_h16[(long long)MAX_N * HD];   // layer-1 output (fp16)
__device__ __half g_x16[(long long)MAX_N * 64];   // x converted to fp16
__device__ __half g_wt11[128 * 64];               // W11x^T fp16 [n][k]
__device__ __half g_wt12[128 * 128];              // W12^T
__device__ __half g_wt21[128 * 128];              // W21x^T
__device__ __half g_wt22[128 * 128];              // W22^T
__device__ int    g_cnt[MAX_N];
__device__ int    g_fill[MAX_N];
__device__ int    g_rowptr[MAX_N + 1];
__device__ int    g_bsum[128];
__device__ int    g_boff[128];
__device__ int2   g_meta[MAX_E];                  // (src, half2(ea0,ea1))

__device__ __forceinline__ void cp16(void* smem_dst, const void* gsrc, int src_bytes) {
    unsigned s = (unsigned)__cvta_generic_to_shared(smem_dst);
    asm volatile("cp.async.ca.shared.global [%0], [%1], 16, %2;"
                 :: "r"(s), "l"(gsrc), "r"(src_bytes));
}
__device__ __forceinline__ void cp_commit() { asm volatile("cp.async.commit_group;"); }
template <int NN>
__device__ __forceinline__ void cp_wait() {
    asm volatile("cp.async.wait_group %0;" :: "n"(NN));
}
__device__ __forceinline__ void mma16816(float* d, const unsigned* a, const unsigned* b) {
    asm volatile("mma.sync.aligned.m16n8k16.row.col.f32.f16.f16.f32 "
                 "{%0,%1,%2,%3}, {%4,%5,%6,%7}, {%8,%9}, {%0,%1,%2,%3};"
                 : "+f"(d[0]), "+f"(d[1]), "+f"(d[2]), "+f"(d[3])
                 : "r"(a[0]), "r"(a[1]), "r"(a[2]), "r"(a[3]),
                   "r"(b[0]), "r"(b[1]));
}

// ============================== CSR build ==================================
__global__ void count_kernel(const int* __restrict__ ei, int* __restrict__ cnt, int E) {
    int e = blockIdx.x * blockDim.x + threadIdx.x;
    if (e < E) atomicAdd(&cnt[ei[E + e]], 1);
}
__global__ void scan_reduce_kernel(const int* __restrict__ cnt, int* __restrict__ bsum, int N) {
    __shared__ int sh[256];
    int base = blockIdx.x * 1024;
    int s = 0;
    for (int i = threadIdx.x; i < 1024; i += 256) {
        int idx = base + i;
        if (idx < N) s += cnt[idx];
    }
    sh[threadIdx.x] = s; __syncthreads();
    for (int off = 128; off > 0; off >>= 1) {
        if (threadIdx.x < off) sh[threadIdx.x] += sh[threadIdx.x + off];
        __syncthreads();
    }
    if (threadIdx.x == 0) bsum[blockIdx.x] = sh[0];
}
__global__ void scan_bsums_kernel(const int* __restrict__ bsum, int* __restrict__ boff,
                                  int nb, int* __restrict__ rowptr, int N, int E) {
    __shared__ int sh[128];
    int t = threadIdx.x;
    int v = (t < nb) ? bsum[t] : 0;
    sh[t] = v; __syncthreads();
#pragma unroll
    for (int off = 1; off < 128; off <<= 1) {
        int u = (t >= off) ? sh[t - off] : 0;
        __syncthreads();
        sh[t] += u;
        __syncthreads();
    }
    if (t < nb) boff[t] = sh[t] - v;
    if (t == 0) rowptr[N] = E;
}
__global__ void scan_block_kernel(const int* __restrict__ cnt, const int* __restrict__ boff,
                                  int* __restrict__ rowptr, int N) {
    __shared__ int sh[1024];
    const int tid = threadIdx.x;
    const int idx = blockIdx.x * 1024 + tid;
    int v = (idx < N) ? cnt[idx] : 0;
    sh[tid] = v; __syncthreads();
#pragma unroll
    for (int off = 1; off < 1024; off <<= 1) {
        int t = (tid >= off) ? sh[tid - off] : 0;
        __syncthreads();
        sh[tid] += t;
        __syncthreads();
    }
    if (idx < N) rowptr[idx] = boff[blockIdx.x] + sh[tid] - v;
}
__global__ void fill_kernel(const int* __restrict__ ei, const float* __restrict__ ea,
                            const int* __restrict__ rowptr, int* __restrict__ fill,
                            int2* __restrict__ meta, int E) {
    int e = blockIdx.x * blockDim.x + threadIdx.x;
    if (e >= E) return;
    int dst = ei[E + e];
    int slot = rowptr[dst] + atomicAdd(&fill[dst], 1);
    float2 ev = *(const float2*)(ea + 2 * e);
    __half2 eh = __floats2half2_rn(ev.x, ev.y);
    meta[slot] = make_int2(ei[e], *(int*)&eh);
}

// ========================= conversion prepasses ============================
__global__ void cvt_x_kernel(const float* __restrict__ x, __half* __restrict__ xh, int n4) {
    int i = blockIdx.x * blockDim.x + threadIdx.x;
    if (i < n4) {
        float4 v = ((const float4*)x)[i];
        __half2 a = __floats2half2_rn(v.x, v.y);
        __half2 b = __floats2half2_rn(v.z, v.w);
        uint2 o;
        o.x = *(unsigned*)&a;
        o.y = *(unsigned*)&b;
        ((uint2*)xh)[i] = o;
    }
}
__global__ void cvt_weights_kernel(const float* __restrict__ W11, const float* __restrict__ W12,
                                   const float* __restrict__ W21, const float* __restrict__ W22,
                                   __half* __restrict__ wt11, __half* __restrict__ wt12,
                                   __half* __restrict__ wt21, __half* __restrict__ wt22) {
    int idx = blockIdx.x * blockDim.x + threadIdx.x;
    if (idx < 8192) {
        int n = idx >> 6, k = idx & 63;
        wt11[idx] = __float2half(W11[k * 128 + n]);
    } else if (idx < 8192 + 16384) {
        int i = idx - 8192;
        int n = i >> 7, k = i & 127;
        wt12[i] = __float2half(W12[k * 128 + n]);
    } else if (idx < 8192 + 32768) {
        int i = idx - 8192 - 16384;
        int n = i >> 7, k = i & 127;
        wt21[i] = __float2half(W21[k * 128 + n]);
    } else if (idx < 8192 + 49152) {
        int i = idx - 8192 - 32768;
        int n = i >> 7, k = i & 127;
        wt22[i] = __float2half(W22[k * 128 + n]);
    }
}

// ======================= tensor-core GEMM ==================================
template <int K, typename OutT, bool BIAS, bool RELU>
__global__ __launch_bounds__(256, 2)
void hgemm_kernel(const __half* __restrict__ A, const __half* __restrict__ Wt,
                  OutT* __restrict__ C, const float* __restrict__ bias,
                  const int* __restrict__ rowptr, int N)
{
    constexpr int BS_LD = K + 8;
    constexpr int AS_LD = 40;
    extern __shared__ __half sh[];
    __half* Bs = sh;
    __half* As = sh + 128 * BS_LD;

    const int tid  = threadIdx.x;
    const int lane = tid & 31;
    const int wid  = tid >> 5;
    const int wm   = (wid & 3) * 32;
    const int wn   = (wid >> 2) * 64;
    const int row0 = blockIdx.x * 128;

    {
        int r = tid >> 1;
        int cb = (tid & 1) * (K / 2);
#pragma unroll
        for (int j = 0; j < K / 16; ++j)
            cp16(&Bs[r * BS_LD + cb + j * 8], &Wt[r * K + cb + j * 8], 16);
    }
    auto loadA = [&](int buf, int k0) {
        int r = tid >> 1;
        int h0 = (tid & 1) * 16;
        int row = row0 + r;
        int ok = (row < N) ? 16 : 0;
        const __half* ap = &A[(long long)row * K + k0 + h0];
        __half* dp = &As[(buf * 128 + r) * AS_LD + h0];
        cp16(dp,     ap,     ok);
        cp16(dp + 8, ap + 8, ok);
    };
    loadA(0, 0);
    cp_commit();

    float d[2][8][4];
#pragma unroll
    for (int i = 0; i < 2; ++i)
#pragma unroll
        for (int j = 0; j < 8; ++j)
#pragma unroll
            for (int p = 0; p < 4; ++p) d[i][j][p] = 0.f;

    const int r_ = lane >> 2;
    const int c_ = (lane & 3) * 2;
    constexpr int nt = K / 32;

#pragma unroll 1
    for (int t = 0; t < nt; ++t) {
        const int buf = t & 1;
        if (t + 1 < nt) { loadA(buf ^ 1, (t + 1) * 32); cp_commit(); cp_wait<1>(); }
        else            { cp_wait<0>(); }
        __syncthreads();
#pragma unroll
        for (int ks = 0; ks < 2; ++ks) {
            const int kk = ks * 16;
            unsigned a[2][4], b[8][2];
#pragma unroll
            for (int i = 0; i < 2; ++i) {
                const __half* base = &As[(buf * 128 + wm + i * 16 + r_) * AS_LD + kk + c_];
                a[i][0] = *(const unsigned*)base;
                a[i][1] = *(const unsigned*)(base + 8 * AS_LD);
                a[i][2] = *(const unsigned*)(base + 8);
                a[i][3] = *(const unsigned*)(base + 8 * AS_LD + 8);
            }
#pragma unroll
            for (int j = 0; j < 8; ++j) {
                const __half* bb = &Bs[(wn + j * 8 + r_) * BS_LD + t * 32 + kk + c_];
                b[j][0] = *(const unsigned*)bb;
                b[j][1] = *(const unsigned*)(bb + 8);
            }
#pragma unroll
            for (int i = 0; i < 2; ++i)
#pragma unroll
                for (int j = 0; j < 8; ++j)
                    mma16816(d[i][j], a[i], b[j]);
        }
        __syncthreads();
    }

#pragma unroll
    for (int i = 0; i < 2; ++i) {
#pragma unroll
        for (int hf = 0; hf < 2; ++hf) {
            int row = row0 + wm + i * 16 + hf * 8 + r_;
            if (row >= N) continue;
            float mult = 0.f;
            if (BIAS) mult = (float)(rowptr[row + 1] - rowptr[row]) + 1.0f;
#pragma unroll
            for (int j = 0; j < 8; ++j) {
                float v0 = d[i][j][hf * 2 + 0];
                float v1 = d[i][j][hf * 2 + 1];
                int col = wn + j * 8 + c_;
                if (BIAS) { v0 += mult * bias[col]; v1 += mult * bias[col + 1]; }
                if (RELU) { v0 = fmaxf(v0, 0.f); v1 = fmaxf(v1, 0.f); }
                if constexpr (sizeof(OutT) == 2) {
                    __half2 hv = __floats2half2_rn(v0, v1);
                    *(__half2*)((__half*)C + (long long)row * 128 + col) = hv;
                } else {
                    *(float2*)((float*)C + (long long)row * 128 + col) = make_float2(v0, v1);
                }
            }
        }
    }
}

// ========================= CSR gather-aggregate ============================
__device__ __forceinline__ float4 cvtP4(uint2 raw) {
    __half2 h0 = *(__half2*)&raw.x;
    __half2 h1 = *(__half2*)&raw.y;
    float2 f0 = __half22float2(h0);
    float2 f1 = __half22float2(h1);
    return make_float4(f0.x, f0.y, f1.x, f1.y);
}

__global__ __launch_bounds__(256)
void gather_kernel(const int* __restrict__ rowptr, const int2* __restrict__ meta,
                   const __half* __restrict__ P, __half* __restrict__ agg,
                   const float* __restrict__ w0, const float* __restrict__ w1,
                   const float* __restrict__ b, int N)
{
    const int lane = threadIdx.x & 31;
    const int c = lane * 4;
    const int warp = blockIdx.x * (blockDim.x >> 5) + (threadIdx.x >> 5);
    const int nwarps = gridDim.x * (blockDim.x >> 5);

    const float4 wa = *(const float4*)(w0 + c);
    const float4 wb = *(const float4*)(w1 + c);
    const float4 bb = *(const float4*)(b + c);

    for (int n = warp; n < N; n += nwarps) {
        const int s = rowptr[n];
        const int e = rowptr[n + 1];

        // self loop (ea = 1,1)
        float4 ps = cvtP4(*(const uint2*)(P + (long long)n * HD + c));
        float4 acc;
        acc.x = fmaxf(ps.x + wa.x + wb.x + bb.x, 0.f);
        acc.y = fmaxf(ps.y + wa.y + wb.y + bb.y, 0.f);
        acc.z = fmaxf(ps.z + wa.z + wb.z + bb.z, 0.f);
        acc.w = fmaxf(ps.w + wa.w + wb.w + bb.w, 0.f);

        int j = s;
        for (; j + 8 <= e; j += 8) {
            uint2 raw[8];
            int2 mt[8];
#pragma unroll
            for (int q = 0; q < 8; ++q) {
                mt[q] = meta[j + q];
                raw[q] = *(const uint2*)(P + (long long)mt[q].x * HD + c);
            }
#pragma unroll
            for (int q = 0; q < 8; ++q) {
                float2 ef = __half22float2(*(__half2*)&mt[q].y);
                float4 p = cvtP4(raw[q]);
                acc.x += fmaxf(fmaf(ef.x, wa.x, fmaf(ef.y, wb.x, p.x + bb.x)), 0.f);
                acc.y += fmaxf(fmaf(ef.x, wa.y, fmaf(ef.y, wb.y, p.y + bb.y)), 0.f);
                acc.z += fmaxf(fmaf(ef.x, wa.z, fmaf(ef.y, wb.z, p.z + bb.z)), 0.f);
                acc.w += fmaxf(fmaf(ef.x, wa.w, fmaf(ef.y, wb.w, p.w + bb.w)), 0.f);
            }
        }
        if (j + 4 <= e) {
            uint2 raw[4];
            int2 mt[4];
#pragma unroll
            for (int q = 0; q < 4; ++q) {
                mt[q] = meta[j + q];
                raw[q] = *(const uint2*)(P + (long long)mt[q].x * HD + c);
            }
#pragma unroll
            for (int q = 0; q < 4; ++q) {
                float2 ef = __half22float2(*(__half2*)&mt[q].y);
                float4 p = cvtP4(raw[q]);
                acc.x += fmaxf(fmaf(ef.x, wa.x, fmaf(ef.y, wb.x, p.x + bb.x)), 0.f);
                acc.y += fmaxf(fmaf(ef.x, wa.y, fmaf(ef.y, wb.y, p.y + bb.y)), 0.f);
                acc.z += fmaxf(fmaf(ef.x, wa.z, fmaf(ef.y, wb.z, p.z + bb.z)), 0.f);
                acc.w += fmaxf(fmaf(ef.x, wa.w, fmaf(ef.y, wb.w, p.w + bb.w)), 0.f);
            }
            j += 4;
        }
        for (; j < e; ++j) {
            int2 mq = meta[j];
            float2 ef = __half22float2(*(__half2*)&mq.y);
            float4 p = cvtP4(*(const uint2*)(P + (long long)mq.x * HD + c));
            acc.x += fmaxf(fmaf(ef.x, wa.x, fmaf(ef.y, wb.x, p.x + bb.x)), 0.f);
            acc.y += fmaxf(fmaf(ef.x, wa.y, fmaf(ef.y, wb.y, p.y + bb.y)), 0.f);
            acc.z += fmaxf(fmaf(ef.x, wa.z, fmaf(ef.y, wb.z, p.z + bb.z)), 0.f);
            acc.w += fmaxf(fmaf(ef.x, wa.w, fmaf(ef.y, wb.w, p.w + bb.w)), 0.f);
        }
        __half2 o0 = __floats2half2_rn(acc.x, acc.y);
        __half2 o1 = __floats2half2_rn(acc.z, acc.w);
        uint2 st;
        st.x = *(unsigned*)&o0;
        st.y = *(unsigned*)&o1;
        *(uint2*)(agg + (long long)n * HD + c) = st;
    }
}

// ---------------------------------------------------------------------------
extern "C" void kernel_launch(void* const* d_in, const int* in_sizes, int n_in,
                              void* d_out, int out_size)
{
    const float* x   = (const float*)d_in[0];
    const int*   ei  = (const int*)d_in[1];
    const float* ea  = (const float*)d_in[2];
    const float* W11 = (const float*)d_in[3];
    const float* b11 = (const float*)d_in[4];
    const float* W12 = (const float*)d_in[5];
    const float* b12 = (const float*)d_in[6];
    const float* W21 = (const float*)d_in[7];
    const float* b21 = (const float*)d_in[8];
    const float* W22 = (const float*)d_in[9];
    const float* b22 = (const float*)d_in[10];
    float* out = (float*)d_out;

    const int IN_DIM = 64;
    const int N = in_sizes[0] / IN_DIM;
    const int E = in_sizes[1] / 2;

    __half *P, *agg16, *h16, *x16, *wt11, *wt12, *wt21, *wt22;
    int *cnt, *fill, *rowptr, *bsum, *boff;
    int2* meta;
    cudaGetSymbolAddress((void**)&P,      g_P);
    cudaGetSymbolAddress((void**)&agg16,  g_agg16);
    cudaGetSymbolAddress((void**)&h16,    g_h16);
    cudaGetSymbolAddress((void**)&x16,    g_x16);
    cudaGetSymbolAddress((void**)&wt11,   g_wt11);
    cudaGetSymbolAddress((void**)&wt12,   g_wt12);
    cudaGetSymbolAddress((void**)&wt21,   g_wt21);
    cudaGetSymbolAddress((void**)&wt22,   g_wt22);
    cudaGetSymbolAddress((void**)&cnt,    g_cnt);
    cudaGetSymbolAddress((void**)&fill,   g_fill);
    cudaGetSymbolAddress((void**)&rowptr, g_rowptr);
    cudaGetSymbolAddress((void**)&bsum,   g_bsum);
    cudaGetSymbolAddress((void**)&boff,   g_boff);
    cudaGetSymbolAddress((void**)&meta,   g_meta);

    const int gemm_blocks = (N + 127) / 128;
    const int gath_blocks = 148 * 16;
    const int nb = (N + 1023) / 1024;
    const int smem128 = (128 * (128 + 8) + 2 * 128 * 40) * 2;  // 55296 B
    const int smem64  = (128 * (64 + 8)  + 2 * 128 * 40) * 2;  // 38912 B

    static cudaStream_t s2 = nullptr;
    static cudaEvent_t evFork = nullptr, evCSR = nullptr;
    static int attr_set = 0;
    if (!attr_set) {
        cudaFuncSetAttribute(hgemm_kernel<64,  __half, false, false>,
                             cudaFuncAttributeMaxDynamicSharedMemorySize, smem64);
        cudaFuncSetAttribute(hgemm_kernel<128, __half, true,  true>,
                             cudaFuncAttributeMaxDynamicSharedMemorySize, smem128);
        cudaFuncSetAttribute(hgemm_kernel<128, __half, false, false>,
                             cudaFuncAttributeMaxDynamicSharedMemorySize, smem128);
        cudaFuncSetAttribute(hgemm_kernel<128, float,  true,  false>,
                             cudaFuncAttributeMaxDynamicSharedMemorySize, smem128);
        cudaStreamCreateWithFlags(&s2, cudaStreamNonBlocking);
        cudaEventCreateWithFlags(&evFork, cudaEventDisableTiming);
        cudaEventCreateWithFlags(&evCSR,  cudaEventDisableTiming);
        attr_set = 1;
    }

    // ---- fork: CSR build on side stream, conversions + GEMM1 on main ----
    cudaEventRecord(evFork, 0);
    cudaStreamWaitEvent(s2, evFork, 0);

    // side stream: CSR build chain
    cudaMemsetAsync(cnt,  0, N * sizeof(int), s2);
    cudaMemsetAsync(fill, 0, N * sizeof(int), s2);
    count_kernel<<<(E + 255) / 256, 256, 0, s2>>>(ei, cnt, E);
    scan_reduce_kernel<<<nb, 256, 0, s2>>>(cnt, bsum, N);
    scan_bsums_kernel<<<1, 128, 0, s2>>>(bsum, boff, nb, rowptr, N, E);
    scan_block_kernel<<<nb, 1024, 0, s2>>>(cnt, boff, rowptr, N);
    fill_kernel<<<(E + 255) / 256, 256, 0, s2>>>(ei, ea, rowptr, fill, meta, E);
    cudaEventRecord(evCSR, s2);

    // main stream: conversions + P1 GEMM (independent of CSR)
    cvt_x_kernel<<<(N * 16 + 255) / 256, 256>>>(x, x16, N * 16);
    cvt_weights_kernel<<<(8192 + 49152 + 255) / 256, 256>>>(
        W11, W12, W21, W22, wt11, wt12, wt21, wt22);
    hgemm_kernel<64, __half, false, false><<<gemm_blocks, 256, smem64>>>(
        x16, wt11, P, nullptr, nullptr, N);

    // join: gather needs CSR
    cudaStreamWaitEvent(0, evCSR, 0);

    // ---- layer 1 ----
    gather_kernel<<<gath_blocks, 256>>>(rowptr, meta, P, agg16,
                                        W11 + 64 * 128, W11 + 65 * 128, b11, N);
    hgemm_kernel<128, __half, true, true><<<gemm_blocks, 256, smem128>>>(
        agg16, wt12, h16, b12, rowptr, N);

    // ---- layer 2 ----
    hgemm_kernel<128, __half, false, false><<<gemm_blocks, 256, smem128>>>(
        h16, wt21, P, nullptr, nullptr, N);
    gather_kernel<<<gath_blocks, 256>>>(rowptr, meta, P, agg16,
                                        W21 + 128 * 128, W21 + 129 * 128, b21, N);
    hgemm_kernel<128, float, true, false><<<gemm_blocks, 256, smem128>>>(
        agg16, wt22, out, b22, rowptr, N);
}